// round 3
// baseline (speedup 1.0000x reference)
#include <cuda_runtime.h>

#define NN 50000
#define EE 800000
#define GG 2500
#define DD 96
#define DEE 16
#define ND (NN*DD)

// ---------------- scratch (no allocations allowed) ----------------
__device__ __align__(16) float g_bufA[ND];
__device__ __align__(16) float g_bufB[ND];
__device__ __align__(16) float g_bufC[ND];
__device__ __align__(16) float g_sum[DD];
__device__ __align__(16) float g_sumsq[DD];
__device__ __align__(16) float g_scale[DD];
__device__ __align__(16) float g_shift[DD];
__device__ __align__(16) float g_pool[GG];

// ---------------- small kernels ----------------
__global__ void k_zero() {
    int i = blockIdx.x * blockDim.x + threadIdx.x;
    if (i < DD) { g_sum[i] = 0.f; g_sumsq[i] = 0.f; }
    if (i < GG) g_pool[i] = 0.f;
}

// h = (1+eps[0]) * x   (layer 0; x stays the gather source)
__global__ void k_init0(const float* __restrict__ x, const float* __restrict__ eps,
                        float* __restrict__ h) {
    int i = blockIdx.x * blockDim.x + threadIdx.x;
    if (i >= ND / 4) return;
    float s = 1.f + __ldg(eps);
    float4 v = __ldg((const float4*)x + i);
    v.x *= s; v.y *= s; v.z *= s; v.w *= s;
    ((float4*)h)[i] = v;
}

// xn = leaky(xraw*scale+shift); write xn; h = (1+eps[l]) * xn
__global__ void k_init(const float* __restrict__ xraw, const float* __restrict__ eps, int l,
                       float* __restrict__ xn, float* __restrict__ h) {
    int i = blockIdx.x * blockDim.x + threadIdx.x;
    if (i >= ND / 4) return;
    int c4 = i % (DD / 4);
    float4 sc = ((const float4*)g_scale)[c4];
    float4 sh = ((const float4*)g_shift)[c4];
    float4 v = __ldg((const float4*)xraw + i);
    v.x = v.x * sc.x + sh.x; v.x = v.x > 0.f ? v.x : 0.01f * v.x;
    v.y = v.y * sc.y + sh.y; v.y = v.y > 0.f ? v.y : 0.01f * v.y;
    v.z = v.z * sc.z + sh.z; v.z = v.z > 0.f ? v.z : 0.01f * v.z;
    v.w = v.w * sc.w + sh.w; v.w = v.w > 0.f ? v.w : 0.01f * v.w;
    ((float4*)xn)[i] = v;
    float s = 1.f + __ldg(eps + l);
    float4 hv; hv.x = s * v.x; hv.y = s * v.y; hv.z = s * v.z; hv.w = s * v.w;
    ((float4*)h)[i] = hv;
}

// per-edge: msg = relu(x[src] + edge_attr@We + be); red-add into h[dst]
__global__ void k_edge(const float* __restrict__ x, const int* __restrict__ ei,
                       const float* __restrict__ ea, const float* __restrict__ We,
                       const float* __restrict__ be, float* __restrict__ h) {
    __shared__ __align__(16) float sW[DEE * DD];
    __shared__ __align__(16) float sbe[DD];
    int tid = threadIdx.x;
    for (int i = tid; i < DEE * DD; i += blockDim.x) sW[i] = __ldg(We + i);
    for (int i = tid; i < DD; i += blockDim.x) sbe[i] = __ldg(be + i);
    __syncthreads();

    int lane = tid & 31;
    int warp = (blockIdx.x * blockDim.x + tid) >> 5;
    int nw = (gridDim.x * blockDim.x) >> 5;
    const float4* sW4 = (const float4*)sW;
    const float4* sbe4 = (const float4*)sbe;

    for (int e = warp; e < EE; e += nw) {
        int src = __ldg(ei + e);
        int dst = __ldg(ei + EE + e);
        float av = (lane < DEE) ? __ldg(ea + (size_t)e * DEE + lane) : 0.f;
        float ak[DEE];
#pragma unroll
        for (int k = 0; k < DEE; k++) ak[k] = __shfl_sync(0xffffffffu, av, k);
        if (lane < DD / 4) {
            float4 acc = sbe4[lane];
#pragma unroll
            for (int k = 0; k < DEE; k++) {
                float4 w = sW4[k * (DD / 4) + lane];
                acc.x += ak[k] * w.x; acc.y += ak[k] * w.y;
                acc.z += ak[k] * w.z; acc.w += ak[k] * w.w;
            }
            float4 xv = __ldg((const float4*)(x + (size_t)src * DD) + lane);
            float4 m;
            m.x = xv.x + acc.x; m.x = m.x > 0.f ? m.x : 0.f;
            m.y = xv.y + acc.y; m.y = m.y > 0.f ? m.y : 0.f;
            m.z = xv.z + acc.z; m.z = m.z > 0.f ? m.z : 0.f;
            m.w = xv.w + acc.w; m.w = m.w > 0.f ? m.w : 0.f;
            float* p = h + (size_t)dst * DD + lane * 4;
            asm volatile("red.global.add.v4.f32 [%0], {%1, %2, %3, %4};"
                         :: "l"(p), "f"(m.x), "f"(m.y), "f"(m.z), "f"(m.w) : "memory");
        }
    }
}

// tiled GEMM: out[M,96] = op(A)[M,96] @ W[96,96] + bias; optional BN-stats of out.
// NORM: A elements get leaky(a*scale[k]+shift[k]) on load.
template<bool NORM, bool STATS>
__global__ void k_gemm(const float* __restrict__ A, const float* __restrict__ W,
                       const float* __restrict__ bias, float* __restrict__ out) {
    extern __shared__ float smem[];
    float* sA = smem;               // 64*96
    float* sW = smem + 64 * DD;     // 96*96
    int tid = threadIdx.x;
    int tile0 = blockIdx.x * 64;

    // load W (9216 floats = 2304 float4)
    {
        float4* d = (float4*)sW;
        const float4* s = (const float4*)W;
#pragma unroll
        for (int j = 0; j < 9; j++) d[j * 256 + tid] = __ldg(s + j * 256 + tid);
    }
    // load A tile (64x96 = 1536 float4)
#pragma unroll
    for (int j = 0; j < 6; j++) {
        int f4 = j * 256 + tid;
        int row = f4 / (DD / 4);
        int c4 = f4 % (DD / 4);
        int rg = tile0 + row;
        float4 v = make_float4(0.f, 0.f, 0.f, 0.f);
        if (rg < NN) {
            v = __ldg((const float4*)A + (size_t)rg * (DD / 4) + c4);
            if (NORM) {
                float4 sc = ((const float4*)g_scale)[c4];
                float4 sh = ((const float4*)g_shift)[c4];
                v.x = v.x * sc.x + sh.x; v.x = v.x > 0.f ? v.x : 0.01f * v.x;
                v.y = v.y * sc.y + sh.y; v.y = v.y > 0.f ? v.y : 0.01f * v.y;
                v.z = v.z * sc.z + sh.z; v.z = v.z > 0.f ? v.z : 0.01f * v.z;
                v.w = v.w * sc.w + sh.w; v.w = v.w > 0.f ? v.w : 0.01f * v.w;
            }
        }
        ((float4*)sA)[f4] = v;
    }
    __syncthreads();

    int tx = tid & 31, ty = tid >> 5;
    float acc[8][3];
#pragma unroll
    for (int i = 0; i < 8; i++) { acc[i][0] = 0.f; acc[i][1] = 0.f; acc[i][2] = 0.f; }

#pragma unroll 4
    for (int k = 0; k < DD; k++) {
        float b0 = sW[k * DD + tx];
        float b1 = sW[k * DD + tx + 32];
        float b2 = sW[k * DD + tx + 64];
#pragma unroll
        for (int i = 0; i < 8; i++) {
            float a = sA[(ty * 8 + i) * DD + k];
            acc[i][0] += a * b0; acc[i][1] += a * b1; acc[i][2] += a * b2;
        }
    }

    float bb0 = __ldg(bias + tx), bb1 = __ldg(bias + tx + 32), bb2 = __ldg(bias + tx + 64);
    float ps0 = 0.f, ps1 = 0.f, ps2 = 0.f, pq0 = 0.f, pq1 = 0.f, pq2 = 0.f;
#pragma unroll
    for (int i = 0; i < 8; i++) {
        int rg = tile0 + ty * 8 + i;
        if (rg < NN) {
            float v0 = acc[i][0] + bb0;
            float v1 = acc[i][1] + bb1;
            float v2 = acc[i][2] + bb2;
            out[(size_t)rg * DD + tx] = v0;
            out[(size_t)rg * DD + tx + 32] = v1;
            out[(size_t)rg * DD + tx + 64] = v2;
            if (STATS) {
                ps0 += v0; ps1 += v1; ps2 += v2;
                pq0 += v0 * v0; pq1 += v1 * v1; pq2 += v2 * v2;
            }
        }
    }
    if (STATS) {
        __syncthreads();
        float* ss = sA;        // reuse
        float* sq = sA + DD;
        if (tid < 2 * DD) sA[tid] = 0.f;
        __syncthreads();
        atomicAdd(ss + tx, ps0); atomicAdd(ss + tx + 32, ps1); atomicAdd(ss + tx + 64, ps2);
        atomicAdd(sq + tx, pq0); atomicAdd(sq + tx + 32, pq1); atomicAdd(sq + tx + 64, pq2);
        __syncthreads();
        if (tid < DD) {
            atomicAdd(g_sum + tid, ss[tid]);
            atomicAdd(g_sumsq + tid, sq[tid]);
        }
    }
}

// stats -> scale/shift; rezero stats
__global__ void k_bnprep(const float* __restrict__ g, const float* __restrict__ bt) {
    int c = threadIdx.x;
    if (c >= DD) return;
    float s = g_sum[c], q = g_sumsq[c];
    float mean = s * (1.f / NN);
    float var = q * (1.f / NN) - mean * mean;
    float sc = __ldg(g + c) * rsqrtf(var + 1e-5f);
    g_scale[c] = sc;
    g_shift[c] = __ldg(bt + c) - mean * sc;
    g_sum[c] = 0.f;
    g_sumsq[c] = 0.f;
}

// per-node: out = dot(x, fW[:96]) + fb ; pool[batch] += dot(x, fW[96:])
__global__ void k_final1(const float* __restrict__ x, const int* __restrict__ batch,
                         const float* __restrict__ fW, const float* __restrict__ fb,
                         float* __restrict__ out) {
    __shared__ float sfw[2 * DD];
    int tid = threadIdx.x;
    for (int i = tid; i < 2 * DD; i += blockDim.x) sfw[i] = __ldg(fW + i);
    __syncthreads();
    int lane = tid & 31;
    int node = (blockIdx.x * blockDim.x + tid) >> 5;
    if (node >= NN) return;
    const float* xr = x + (size_t)node * DD;
    float v0 = __ldg(xr + lane), v1 = __ldg(xr + lane + 32), v2 = __ldg(xr + lane + 64);
    float lo = v0 * sfw[lane] + v1 * sfw[lane + 32] + v2 * sfw[lane + 64];
    float hi = v0 * sfw[DD + lane] + v1 * sfw[DD + lane + 32] + v2 * sfw[DD + lane + 64];
#pragma unroll
    for (int o = 16; o; o >>= 1) {
        lo += __shfl_down_sync(0xffffffffu, lo, o);
        hi += __shfl_down_sync(0xffffffffu, hi, o);
    }
    if (lane == 0) {
        out[node] = lo + __ldg(fb);
        atomicAdd(g_pool + __ldg(batch + node), hi);
    }
}

__global__ void k_final2(float* __restrict__ out, const int* __restrict__ batch) {
    int i = blockIdx.x * blockDim.x + threadIdx.x;
    if (i < NN) out[i] += g_pool[__ldg(batch + i)];
}

// ---------------- launch ----------------
extern "C" void kernel_launch(void* const* d_in, const int* in_sizes, int n_in,
                              void* d_out, int out_size) {
    const float* x = (const float*)d_in[0];
    const int* ei = (const int*)d_in[1];       // int32 (JAX x64 disabled)
    const float* ea = (const float*)d_in[2];
    const int* batch = (const int*)d_in[3];    // int32
    const float* We = (const float*)d_in[4];
    const float* be = (const float*)d_in[5];
    const float* eps = (const float*)d_in[6];
    const float* W1 = (const float*)d_in[7];
    const float* b1 = (const float*)d_in[8];
    const float* g1 = (const float*)d_in[9];
    const float* bt1 = (const float*)d_in[10];
    const float* W2 = (const float*)d_in[11];
    const float* b2 = (const float*)d_in[12];
    const float* g_o = (const float*)d_in[13];
    const float* bt_o = (const float*)d_in[14];
    const float* fW = (const float*)d_in[15];
    const float* fb = (const float*)d_in[16];
    float* out = (float*)d_out;

    float *A, *B, *C;
    cudaGetSymbolAddress((void**)&A, g_bufA);
    cudaGetSymbolAddress((void**)&B, g_bufB);
    cudaGetSymbolAddress((void**)&C, g_bufC);

    const int SMEM_GEMM = (64 * DD + DD * DD) * sizeof(float);  // 60 KB
    cudaFuncSetAttribute(k_gemm<false, true>, cudaFuncAttributeMaxDynamicSharedMemorySize, SMEM_GEMM);
    cudaFuncSetAttribute(k_gemm<true, true>, cudaFuncAttributeMaxDynamicSharedMemorySize, SMEM_GEMM);
    cudaFuncSetAttribute(k_gemm<true, false>, cudaFuncAttributeMaxDynamicSharedMemorySize, SMEM_GEMM);

    const int GEMM_BLOCKS = (NN + 63) / 64;          // 782
    const int INIT_BLOCKS = (ND / 4 + 255) / 256;    // 4688
    const int EDGE_BLOCKS = 2048;

    k_zero<<<(GG + 255) / 256, 256>>>();

    // ---- layer 0 ----
    k_init0<<<INIT_BLOCKS, 256>>>(x, eps, A);
    k_edge<<<EDGE_BLOCKS, 128>>>(x, ei, ea, We, be, A);
    k_gemm<false, true><<<GEMM_BLOCKS, 256, SMEM_GEMM>>>(A, W1, b1, B);
    k_bnprep<<<1, DD>>>(g1, bt1);
    k_gemm<true, true><<<GEMM_BLOCKS, 256, SMEM_GEMM>>>(B, W2, b2, C);
    k_bnprep<<<1, DD>>>(g_o, bt_o);

    // ---- layer 1 ----
    k_init<<<INIT_BLOCKS, 256>>>(C, eps, 1, B, A);   // xnorm->B, h->A
    k_edge<<<EDGE_BLOCKS, 128>>>(B, ei, ea, We + DEE * DD, be + DD, A);
    k_gemm<false, true><<<GEMM_BLOCKS, 256, SMEM_GEMM>>>(A, W1 + DD * DD, b1 + DD, C);
    k_bnprep<<<1, DD>>>(g1 + DD, bt1 + DD);
    k_gemm<true, true><<<GEMM_BLOCKS, 256, SMEM_GEMM>>>(C, W2 + DD * DD, b2 + DD, A);
    k_bnprep<<<1, DD>>>(g_o + DD, bt_o + DD);

    // ---- layer 2 ----
    k_init<<<INIT_BLOCKS, 256>>>(A, eps, 2, C, B);   // xnorm->C, h->B
    k_edge<<<EDGE_BLOCKS, 128>>>(C, ei, ea, We + 2 * DEE * DD, be + 2 * DD, B);
    k_gemm<false, true><<<GEMM_BLOCKS, 256, SMEM_GEMM>>>(B, W1 + 2 * DD * DD, b1 + 2 * DD, A);
    k_bnprep<<<1, DD>>>(g1 + 2 * DD, bt1 + 2 * DD);
    k_gemm<true, false><<<GEMM_BLOCKS, 256, SMEM_GEMM>>>(A, W2 + 2 * DD * DD, b2 + 2 * DD, B);

    // ---- readout ----
    k_final1<<<(NN * 32 + 127) / 128, 128>>>(B, batch, fW, fb, out);
    k_final2<<<(NN + 255) / 256, 256>>>(out, batch);
}